// round 1
// baseline (speedup 1.0000x reference)
#include <cuda_runtime.h>
#include <cstdint>

#define NB   16
#define NC   21
#define ND   512
#define HW   4096
#define NR   (NB*NC)   /* 336 */
#define RP   384
#define LABW 513

// -------- device scratch (no allocations allowed) --------
__device__ unsigned char g_lab[NB * HW];        // resized labels, u8
__device__ int           g_cnt[NR];             // per (b,c) pixel counts
__device__ float         g_sums[NR * ND];       // pooled sums
__device__ float         g_P[RP * ND];          // normalized prototypes (padded)
__device__ float         g_S4[4][RP * RP];      // k-split Gram partials

// ============================================================
// K1: bilinear label resize (jax.image.resize bilinear, antialias=False,
// fp32, H contracted first then W), per-class counts, zero d_out.
// ============================================================
__global__ __launch_bounds__(256) void k1_labels(const int* __restrict__ labels,
                                                 float* __restrict__ out)
{
    int b = blockIdx.x;
    int tid = threadIdx.x;
    __shared__ int scnt[NC];
    if (tid < NC) scnt[tid] = 0;
    __syncthreads();

    const int* lb = labels + (size_t)b * (LABW * LABW);

    for (int k = 0; k < 16; k++) {
        int o  = tid + 256 * k;
        int oy = o >> 6, ox = o & 63;

        // ---- y weights (replicate jax compute_weight_mat, fp32) ----
        float sy  = __fsub_rn(__fmul_rn((float)oy + 0.5f, 8.015625f), 0.5f);
        int   y0  = (int)floorf(sy);
        float fy  = __fsub_rn(sy, (float)y0);
        float wy0 = __fsub_rn(1.0f, fy);
        float xy1 = __fsub_rn((float)(y0 + 1), sy);
        float wy1 = __fsub_rn(1.0f, xy1);
        float ty  = __fadd_rn(wy0, wy1);
        wy0 = __fdiv_rn(wy0, ty);
        wy1 = __fdiv_rn(wy1, ty);

        // ---- x weights ----
        float sx  = __fsub_rn(__fmul_rn((float)ox + 0.5f, 8.015625f), 0.5f);
        int   x0  = (int)floorf(sx);
        float fx  = __fsub_rn(sx, (float)x0);
        float wx0 = __fsub_rn(1.0f, fx);
        float xx1 = __fsub_rn((float)(x0 + 1), sx);
        float wx1 = __fsub_rn(1.0f, xx1);
        float tx  = __fadd_rn(wx0, wx1);
        wx0 = __fdiv_rn(wx0, tx);
        wx1 = __fdiv_rn(wx1, tx);

        float v00 = (float)lb[y0 * LABW + x0];
        float v01 = (float)lb[y0 * LABW + x0 + 1];
        float v10 = (float)lb[(y0 + 1) * LABW + x0];
        float v11 = (float)lb[(y0 + 1) * LABW + x0 + 1];

        // contract H first, then W (matches jax einsum dim order)
        float t0 = __fadd_rn(__fmul_rn(wy0, v00), __fmul_rn(wy1, v10));
        float t1 = __fadd_rn(__fmul_rn(wy0, v01), __fmul_rn(wy1, v11));
        float v  = __fadd_rn(__fmul_rn(wx0, t0), __fmul_rn(wx1, t1));

        int li = (int)v;   // truncation toward zero (values >= 0)
        g_lab[b * HW + o] = (unsigned char)li;
        atomicAdd(&scnt[li], 1);
    }
    __syncthreads();
    if (tid < NC) g_cnt[b * NC + tid] = scnt[tid];
    if (b == 0 && tid == 0) out[0] = 0.0f;
}

// ============================================================
// K2: masked pooling. One block per (b,d). 128 threads.
// Shared accumulators sacc[c*128+tid]: 128 % 32 == 0 ->
// bank = tid%32 for every class -> conflict-free, no atomics.
// ============================================================
__global__ __launch_bounds__(128) void k2_pool(const float* __restrict__ feat)
{
    __shared__ float sacc[NC * 128];
    int tid = threadIdx.x;
    int bd  = blockIdx.x;          // b*512 + d
    int b   = bd >> 9;
    int d   = bd & 511;

#pragma unroll
    for (int c = 0; c < NC; c++) sacc[c * 128 + tid] = 0.0f;
    __syncthreads();

    const float4*       f4 = (const float4*)(feat + (size_t)bd * HW);
    const unsigned int* l4 = (const unsigned int*)g_lab + b * (HW / 4);

    float4       fv[8];
    unsigned int lv[8];
#pragma unroll
    for (int k = 0; k < 8; k++) {
        fv[k] = f4[tid + 128 * k];
        lv[k] = l4[tid + 128 * k];
    }

#pragma unroll
    for (int k = 0; k < 8; k++) {
        unsigned int L = lv[k];
        sacc[((L      ) & 255u) * 128 + tid] += fv[k].x;
        sacc[((L >>  8) & 255u) * 128 + tid] += fv[k].y;
        sacc[((L >> 16) & 255u) * 128 + tid] += fv[k].z;
        sacc[((L >> 24) & 255u) * 128 + tid] += fv[k].w;
    }
    __syncthreads();

    if (tid < NC) {
        float s = 0.0f;
        for (int k = 0; k < 128; k++) s += sacc[tid * 128 + k];
        g_sums[(size_t)(b * NC + tid) * ND + d] = s;
    }
}

// ============================================================
// K3: L2 normalize -> g_P; zero-fill padded rows 336..383
// ============================================================
__global__ __launch_bounds__(128) void k3_norm()
{
    int r = blockIdx.x, tid = threadIdx.x;
    float4* dst = (float4*)(g_P + (size_t)r * ND);
    if (r >= NR) {
        float4 z = make_float4(0.f, 0.f, 0.f, 0.f);
        dst[tid] = z;
        return;
    }
    const float4* src = (const float4*)(g_sums + (size_t)r * ND);
    float4 v = src[tid];
    float ss = v.x * v.x + v.y * v.y + v.z * v.z + v.w * v.w;
#pragma unroll
    for (int o = 16; o; o >>= 1) ss += __shfl_xor_sync(0xffffffffu, ss, o);
    __shared__ float sw[4];
    if ((tid & 31) == 0) sw[tid >> 5] = ss;
    __syncthreads();
    float tot = sw[0] + sw[1] + sw[2] + sw[3];
    float den = fmaxf(sqrtf(tot), 1e-12f);
    float4 o4;
    o4.x = v.x / den; o4.y = v.y / den; o4.z = v.z / den; o4.w = v.w / den;
    dst[tid] = o4;
}

// ============================================================
// K4: Gram = P * P^T, 64x64 tiles, 4x4 micro-tile, k-split 4
// (disjoint partial outputs -> no atomics, no pre-zero)
// ============================================================
__global__ __launch_bounds__(256) void k4_gemm()
{
    __shared__ float As[16][68];
    __shared__ float Bs[16][68];
    int tid = threadIdx.x;
    int tx = tid & 15, ty = tid >> 4;
    int m0 = blockIdx.y * 64, n0 = blockIdx.x * 64, k0 = blockIdx.z * 128;
    int lr = tid >> 2, lq = tid & 3;

    float acc[4][4] = {};

    for (int kt = 0; kt < 128; kt += 16) {
        float4 av = *(const float4*)&g_P[(size_t)(m0 + lr) * ND + k0 + kt + lq * 4];
        float4 bv = *(const float4*)&g_P[(size_t)(n0 + lr) * ND + k0 + kt + lq * 4];
        As[lq * 4 + 0][lr] = av.x; As[lq * 4 + 1][lr] = av.y;
        As[lq * 4 + 2][lr] = av.z; As[lq * 4 + 3][lr] = av.w;
        Bs[lq * 4 + 0][lr] = bv.x; Bs[lq * 4 + 1][lr] = bv.y;
        Bs[lq * 4 + 2][lr] = bv.z; Bs[lq * 4 + 3][lr] = bv.w;
        __syncthreads();
#pragma unroll
        for (int kk = 0; kk < 16; kk++) {
            float4 a = *(const float4*)&As[kk][ty * 4];
            float4 bb = *(const float4*)&Bs[kk][tx * 4];
            float ar[4] = {a.x, a.y, a.z, a.w};
            float br[4] = {bb.x, bb.y, bb.z, bb.w};
#pragma unroll
            for (int ia = 0; ia < 4; ia++)
#pragma unroll
                for (int ib = 0; ib < 4; ib++)
                    acc[ia][ib] += ar[ia] * br[ib];
        }
        __syncthreads();
    }

    float* S = g_S4[blockIdx.z];
#pragma unroll
    for (int ia = 0; ia < 4; ia++) {
        float4 o = make_float4(acc[ia][0], acc[ia][1], acc[ia][2], acc[ia][3]);
        *(float4*)&S[(size_t)(m0 + ty * 4 + ia) * RP + n0 + tx * 4] = o;
    }
}

// ============================================================
// K5: per-class masked LSE + positive mean -> atomicAdd loss
// ============================================================
__global__ __launch_bounds__(256) void k5_loss(float* __restrict__ out)
{
    __shared__ unsigned char pres[NR];
    __shared__ float red0[256], red1[256], red2[256];
    int tid = threadIdx.x;
    int c = blockIdx.x;
    for (int idx = tid; idx < NR; idx += 256) pres[idx] = (g_cnt[idx] > 0) ? 1 : 0;
    __syncthreads();

    int i = tid >> 4, j = tid & 15;
    float s_all = 0.f, s_diag = 0.f, p_sum = 0.f;
    int r1 = i * NC + c;
    if (pres[r1]) {
        for (int e = 0; e < NC; e++) {
            int r2 = j * NC + e;
            if (pres[r2]) {
                size_t idx = (size_t)r1 * RP + r2;
                float s = g_S4[0][idx] + g_S4[1][idx] + g_S4[2][idx] + g_S4[3][idx];
                float v = s / 0.1f;
                float ev = expf(v);
                s_all += ev;
                if (e == c) { s_diag += ev; p_sum += v; }
            }
        }
    }
    red0[tid] = s_all; red1[tid] = s_diag; red2[tid] = p_sum;
    __syncthreads();
    for (int st = 128; st; st >>= 1) {
        if (tid < st) {
            red0[tid] += red0[tid + st];
            red1[tid] += red1[tid + st];
            red2[tid] += red2[tid + st];
        }
        __syncthreads();
    }
    if (tid == 0) {
        int nc = 0;
        for (int ii = 0; ii < NB; ii++) nc += pres[ii * NC + c];
        if (nc > 0) {
            int cnt = nc * nc;
            float lse = logf(red1[0] + red0[0]);   // logaddexp(lse_diag, lse_all)
            float pm  = red2[0] / (float)cnt;
            atomicAdd(out, lse - pm);
        }
    }
}

// ============================================================
extern "C" void kernel_launch(void* const* d_in, const int* in_sizes, int n_in,
                              void* d_out, int out_size)
{
    const float* feat   = (const float*)d_in[0];
    const int*   labels = (const int*)d_in[1];
    float*       out    = (float*)d_out;

    k1_labels<<<NB, 256>>>(labels, out);
    k2_pool<<<NB * ND, 128>>>(feat);
    k3_norm<<<RP, 128>>>();
    k4_gemm<<<dim3(6, 6, 4), 256>>>();
    k5_loss<<<NC, 256>>>(out);
}

// round 2
// speedup vs baseline: 1.0040x; 1.0040x over previous
#include <cuda_runtime.h>
#include <cstdint>

#define NB   16
#define NC   21
#define ND   512
#define HW   4096
#define NR   (NB*NC)   /* 336 */
#define RP   384
#define LABW 513

// -------- device scratch (no allocations allowed) --------
__device__ unsigned char g_lab[NB * HW];        // resized labels, u8
__device__ int           g_cnt[NR];             // per (b,c) pixel counts
__device__ float         g_sums[NR * ND];       // pooled sums
__device__ float         g_P[RP * ND];          // normalized prototypes (padded)
__device__ float         g_S4[4][RP * RP];      // k-split Gram partials

// ============================================================
// K1: bilinear label resize (jax.image.resize bilinear, antialias=False,
// fp32, H contracted first then W), per-class counts, zero d_out.
// ============================================================
__global__ __launch_bounds__(256) void k1_labels(const int* __restrict__ labels,
                                                 float* __restrict__ out)
{
    int b = blockIdx.x;
    int tid = threadIdx.x;
    __shared__ int scnt[NC];
    if (tid < NC) scnt[tid] = 0;
    __syncthreads();

    const int* lb = labels + (size_t)b * (LABW * LABW);

    for (int k = 0; k < 16; k++) {
        int o  = tid + 256 * k;
        int oy = o >> 6, ox = o & 63;

        // ---- y weights (replicate jax compute_weight_mat, fp32) ----
        float sy  = __fsub_rn(__fmul_rn((float)oy + 0.5f, 8.015625f), 0.5f);
        int   y0  = (int)floorf(sy);
        float fy  = __fsub_rn(sy, (float)y0);
        float wy0 = __fsub_rn(1.0f, fy);
        float xy1 = __fsub_rn((float)(y0 + 1), sy);
        float wy1 = __fsub_rn(1.0f, xy1);
        float ty  = __fadd_rn(wy0, wy1);
        wy0 = __fdiv_rn(wy0, ty);
        wy1 = __fdiv_rn(wy1, ty);

        // ---- x weights ----
        float sx  = __fsub_rn(__fmul_rn((float)ox + 0.5f, 8.015625f), 0.5f);
        int   x0  = (int)floorf(sx);
        float fx  = __fsub_rn(sx, (float)x0);
        float wx0 = __fsub_rn(1.0f, fx);
        float xx1 = __fsub_rn((float)(x0 + 1), sx);
        float wx1 = __fsub_rn(1.0f, xx1);
        float tx  = __fadd_rn(wx0, wx1);
        wx0 = __fdiv_rn(wx0, tx);
        wx1 = __fdiv_rn(wx1, tx);

        float v00 = (float)lb[y0 * LABW + x0];
        float v01 = (float)lb[y0 * LABW + x0 + 1];
        float v10 = (float)lb[(y0 + 1) * LABW + x0];
        float v11 = (float)lb[(y0 + 1) * LABW + x0 + 1];

        // contract H first, then W (matches jax einsum dim order)
        float t0 = __fadd_rn(__fmul_rn(wy0, v00), __fmul_rn(wy1, v10));
        float t1 = __fadd_rn(__fmul_rn(wy0, v01), __fmul_rn(wy1, v11));
        float v  = __fadd_rn(__fmul_rn(wx0, t0), __fmul_rn(wx1, t1));

        int li = (int)v;   // truncation toward zero (values >= 0)
        g_lab[b * HW + o] = (unsigned char)li;
        atomicAdd(&scnt[li], 1);
    }
    __syncthreads();
    if (tid < NC) g_cnt[b * NC + tid] = scnt[tid];
    if (b == 0 && tid == 0) out[0] = 0.0f;
}

// ============================================================
// K2: masked pooling. One block per (b,d). 128 threads.
// Shared accumulators sacc[c*128+tid]: 128 % 32 == 0 ->
// bank = tid%32 for every class -> conflict-free, no atomics.
// ============================================================
__global__ __launch_bounds__(128) void k2_pool(const float* __restrict__ feat)
{
    __shared__ float sacc[NC * 128];
    int tid = threadIdx.x;
    int bd  = blockIdx.x;          // b*512 + d
    int b   = bd >> 9;
    int d   = bd & 511;

#pragma unroll
    for (int c = 0; c < NC; c++) sacc[c * 128 + tid] = 0.0f;
    __syncthreads();

    const float4*       f4 = (const float4*)(feat + (size_t)bd * HW);
    const unsigned int* l4 = (const unsigned int*)g_lab + b * (HW / 4);

    float4       fv[8];
    unsigned int lv[8];
#pragma unroll
    for (int k = 0; k < 8; k++) {
        fv[k] = f4[tid + 128 * k];
        lv[k] = l4[tid + 128 * k];
    }

#pragma unroll
    for (int k = 0; k < 8; k++) {
        unsigned int L = lv[k];
        sacc[((L      ) & 255u) * 128 + tid] += fv[k].x;
        sacc[((L >>  8) & 255u) * 128 + tid] += fv[k].y;
        sacc[((L >> 16) & 255u) * 128 + tid] += fv[k].z;
        sacc[((L >> 24) & 255u) * 128 + tid] += fv[k].w;
    }
    __syncthreads();

    if (tid < NC) {
        float s = 0.0f;
        for (int k = 0; k < 128; k++) s += sacc[tid * 128 + k];
        g_sums[(size_t)(b * NC + tid) * ND + d] = s;
    }
}

// ============================================================
// K3: L2 normalize -> g_P; zero-fill padded rows 336..383
// ============================================================
__global__ __launch_bounds__(128) void k3_norm()
{
    int r = blockIdx.x, tid = threadIdx.x;
    float4* dst = (float4*)(g_P + (size_t)r * ND);
    if (r >= NR) {
        float4 z = make_float4(0.f, 0.f, 0.f, 0.f);
        dst[tid] = z;
        return;
    }
    const float4* src = (const float4*)(g_sums + (size_t)r * ND);
    float4 v = src[tid];
    float ss = v.x * v.x + v.y * v.y + v.z * v.z + v.w * v.w;
#pragma unroll
    for (int o = 16; o; o >>= 1) ss += __shfl_xor_sync(0xffffffffu, ss, o);
    __shared__ float sw[4];
    if ((tid & 31) == 0) sw[tid >> 5] = ss;
    __syncthreads();
    float tot = sw[0] + sw[1] + sw[2] + sw[3];
    float den = fmaxf(sqrtf(tot), 1e-12f);
    float4 o4;
    o4.x = v.x / den; o4.y = v.y / den; o4.z = v.z / den; o4.w = v.w / den;
    dst[tid] = o4;
}

// ============================================================
// K4: Gram = P * P^T, 64x64 tiles, 4x4 micro-tile, k-split 4
// (disjoint partial outputs -> no atomics, no pre-zero)
// ============================================================
__global__ __launch_bounds__(256) void k4_gemm()
{
    __shared__ float As[16][68];
    __shared__ float Bs[16][68];
    int tid = threadIdx.x;
    int tx = tid & 15, ty = tid >> 4;
    int m0 = blockIdx.y * 64, n0 = blockIdx.x * 64, k0 = blockIdx.z * 128;
    int lr = tid >> 2, lq = tid & 3;

    float acc[4][4] = {};

    for (int kt = 0; kt < 128; kt += 16) {
        float4 av = *(const float4*)&g_P[(size_t)(m0 + lr) * ND + k0 + kt + lq * 4];
        float4 bv = *(const float4*)&g_P[(size_t)(n0 + lr) * ND + k0 + kt + lq * 4];
        As[lq * 4 + 0][lr] = av.x; As[lq * 4 + 1][lr] = av.y;
        As[lq * 4 + 2][lr] = av.z; As[lq * 4 + 3][lr] = av.w;
        Bs[lq * 4 + 0][lr] = bv.x; Bs[lq * 4 + 1][lr] = bv.y;
        Bs[lq * 4 + 2][lr] = bv.z; Bs[lq * 4 + 3][lr] = bv.w;
        __syncthreads();
#pragma unroll
        for (int kk = 0; kk < 16; kk++) {
            float4 a = *(const float4*)&As[kk][ty * 4];
            float4 bb = *(const float4*)&Bs[kk][tx * 4];
            float ar[4] = {a.x, a.y, a.z, a.w};
            float br[4] = {bb.x, bb.y, bb.z, bb.w};
#pragma unroll
            for (int ia = 0; ia < 4; ia++)
#pragma unroll
                for (int ib = 0; ib < 4; ib++)
                    acc[ia][ib] += ar[ia] * br[ib];
        }
        __syncthreads();
    }

    float* S = g_S4[blockIdx.z];
#pragma unroll
    for (int ia = 0; ia < 4; ia++) {
        float4 o = make_float4(acc[ia][0], acc[ia][1], acc[ia][2], acc[ia][3]);
        *(float4*)&S[(size_t)(m0 + ty * 4 + ia) * RP + n0 + tx * 4] = o;
    }
}

// ============================================================
// K5: per-class masked LSE + positive mean -> atomicAdd loss
// ============================================================
__global__ __launch_bounds__(256) void k5_loss(float* __restrict__ out)
{
    __shared__ unsigned char pres[NR];
    __shared__ float red0[256], red1[256], red2[256];
    int tid = threadIdx.x;
    int c = blockIdx.x;
    for (int idx = tid; idx < NR; idx += 256) pres[idx] = (g_cnt[idx] > 0) ? 1 : 0;
    __syncthreads();

    int i = tid >> 4, j = tid & 15;
    float s_all = 0.f, s_diag = 0.f, p_sum = 0.f;
    int r1 = i * NC + c;
    if (pres[r1]) {
        for (int e = 0; e < NC; e++) {
            int r2 = j * NC + e;
            if (pres[r2]) {
                size_t idx = (size_t)r1 * RP + r2;
                float s = g_S4[0][idx] + g_S4[1][idx] + g_S4[2][idx] + g_S4[3][idx];
                float v = s / 0.1f;
                float ev = expf(v);
                s_all += ev;
                if (e == c) { s_diag += ev; p_sum += v; }
            }
        }
    }
    red0[tid] = s_all; red1[tid] = s_diag; red2[tid] = p_sum;
    __syncthreads();
    for (int st = 128; st; st >>= 1) {
        if (tid < st) {
            red0[tid] += red0[tid + st];
            red1[tid] += red1[tid + st];
            red2[tid] += red2[tid + st];
        }
        __syncthreads();
    }
    if (tid == 0) {
        int nc = 0;
        for (int ii = 0; ii < NB; ii++) nc += pres[ii * NC + c];
        if (nc > 0) {
            int cnt = nc * nc;
            float lse = logf(red1[0] + red0[0]);   // logaddexp(lse_diag, lse_all)
            float pm  = red2[0] / (float)cnt;
            atomicAdd(out, lse - pm);
        }
    }
}

// ============================================================
extern "C" void kernel_launch(void* const* d_in, const int* in_sizes, int n_in,
                              void* d_out, int out_size)
{
    const float* feat   = (const float*)d_in[0];
    const int*   labels = (const int*)d_in[1];
    float*       out    = (float*)d_out;

    k1_labels<<<NB, 256>>>(labels, out);
    k2_pool<<<NB * ND, 128>>>(feat);
    k3_norm<<<RP, 128>>>();
    k4_gemm<<<dim3(6, 6, 4), 256>>>();
    k5_loss<<<NC, 256>>>(out);
}

// round 3
// speedup vs baseline: 1.1320x; 1.1275x over previous
#include <cuda_runtime.h>
#include <cstdint>

#define NB   16
#define NC   21
#define ND   512
#define HW   4096
#define NR   (NB*NC)   /* 336 */
#define RP   384
#define LABW 513
#define KSPL 16

// -------- device scratch (no allocations allowed) --------
__device__ unsigned char g_lab[NB * HW];        // resized labels, u8
__device__ int           g_cnt4[4][NR];         // per-chunk (b,c) pixel counts
__device__ float         g_sums[NR * ND];       // pooled sums
__device__ float         g_P[RP * ND];          // normalized prototypes (padded)
__device__ float         g_S16[KSPL][RP * RP];  // k-split Gram partials
__device__ float         g_S[RP * RP];          // reduced Gram

// ============================================================
// K1: bilinear label resize (jax.image.resize bilinear, antialias=False,
// fp32, H contracted first then W), per-chunk class counts, zero d_out.
// grid (16 images, 4 chunks) x 256 thr, 4 px/thread.
// ============================================================
__global__ __launch_bounds__(256) void k1_labels(const int* __restrict__ labels,
                                                 float* __restrict__ out)
{
    int b = blockIdx.x, chunk = blockIdx.y;
    int tid = threadIdx.x;
    __shared__ int scnt[NC];
    if (tid < NC) scnt[tid] = 0;
    __syncthreads();

    const int* lb = labels + (size_t)b * (LABW * LABW);

    for (int p = 0; p < 4; p++) {
        int o  = chunk * 1024 + tid + 256 * p;
        int oy = o >> 6, ox = o & 63;

        // ---- y weights (replicate jax compute_weight_mat, fp32) ----
        float sy  = __fsub_rn(__fmul_rn((float)oy + 0.5f, 8.015625f), 0.5f);
        int   y0  = (int)floorf(sy);
        float fy  = __fsub_rn(sy, (float)y0);
        float wy0 = __fsub_rn(1.0f, fy);
        float xy1 = __fsub_rn((float)(y0 + 1), sy);
        float wy1 = __fsub_rn(1.0f, xy1);
        float ty  = __fadd_rn(wy0, wy1);
        wy0 = __fdiv_rn(wy0, ty);
        wy1 = __fdiv_rn(wy1, ty);

        // ---- x weights ----
        float sx  = __fsub_rn(__fmul_rn((float)ox + 0.5f, 8.015625f), 0.5f);
        int   x0  = (int)floorf(sx);
        float fx  = __fsub_rn(sx, (float)x0);
        float wx0 = __fsub_rn(1.0f, fx);
        float xx1 = __fsub_rn((float)(x0 + 1), sx);
        float wx1 = __fsub_rn(1.0f, xx1);
        float tx  = __fadd_rn(wx0, wx1);
        wx0 = __fdiv_rn(wx0, tx);
        wx1 = __fdiv_rn(wx1, tx);

        float v00 = (float)lb[y0 * LABW + x0];
        float v01 = (float)lb[y0 * LABW + x0 + 1];
        float v10 = (float)lb[(y0 + 1) * LABW + x0];
        float v11 = (float)lb[(y0 + 1) * LABW + x0 + 1];

        // contract H first, then W (matches jax einsum dim order)
        float t0 = __fadd_rn(__fmul_rn(wy0, v00), __fmul_rn(wy1, v10));
        float t1 = __fadd_rn(__fmul_rn(wy0, v01), __fmul_rn(wy1, v11));
        float v  = __fadd_rn(__fmul_rn(wx0, t0), __fmul_rn(wx1, t1));

        int li = (int)v;   // truncation toward zero (values >= 0)
        g_lab[b * HW + o] = (unsigned char)li;
        atomicAdd(&scnt[li], 1);
    }
    __syncthreads();
    if (tid < NC) g_cnt4[chunk][b * NC + tid] = scnt[tid];
    if (b == 0 && chunk == 0 && tid == 0) out[0] = 0.0f;
}

// ============================================================
// K2: masked pooling. One block per (b,d). 128 threads.
// Shared accumulators sacc[c*128+tid]: 128 % 32 == 0 ->
// bank = tid%32 for every class -> conflict-free, no atomics.
// ============================================================
__global__ __launch_bounds__(128) void k2_pool(const float* __restrict__ feat)
{
    __shared__ float sacc[NC * 128];
    int tid = threadIdx.x;
    int bd  = blockIdx.x;          // b*512 + d
    int b   = bd >> 9;

#pragma unroll
    for (int c = 0; c < NC; c++) sacc[c * 128 + tid] = 0.0f;
    __syncthreads();

    const float4*       f4 = (const float4*)(feat + (size_t)bd * HW);
    const unsigned int* l4 = (const unsigned int*)g_lab + b * (HW / 4);

    float4       fv[8];
    unsigned int lv[8];
#pragma unroll
    for (int k = 0; k < 8; k++) {
        fv[k] = f4[tid + 128 * k];
        lv[k] = l4[tid + 128 * k];
    }

#pragma unroll
    for (int k = 0; k < 8; k++) {
        unsigned int L = lv[k];
        sacc[((L      ) & 255u) * 128 + tid] += fv[k].x;
        sacc[((L >>  8) & 255u) * 128 + tid] += fv[k].y;
        sacc[((L >> 16) & 255u) * 128 + tid] += fv[k].z;
        sacc[((L >> 24) & 255u) * 128 + tid] += fv[k].w;
    }
    __syncthreads();

    if (tid < NC) {
        float s = 0.0f;
        for (int k = 0; k < 128; k++) s += sacc[tid * 128 + k];
        g_sums[(size_t)(b * NC + tid) * ND + (bd & 511)] = s;
    }
}

// ============================================================
// K3: L2 normalize -> g_P; zero-fill padded rows 336..383
// ============================================================
__global__ __launch_bounds__(128) void k3_norm()
{
    int r = blockIdx.x, tid = threadIdx.x;
    float4* dst = (float4*)(g_P + (size_t)r * ND);
    if (r >= NR) {
        dst[tid] = make_float4(0.f, 0.f, 0.f, 0.f);
        return;
    }
    const float4* src = (const float4*)(g_sums + (size_t)r * ND);
    float4 v = src[tid];
    float ss = v.x * v.x + v.y * v.y + v.z * v.z + v.w * v.w;
#pragma unroll
    for (int o = 16; o; o >>= 1) ss += __shfl_xor_sync(0xffffffffu, ss, o);
    __shared__ float sw[4];
    if ((tid & 31) == 0) sw[tid >> 5] = ss;
    __syncthreads();
    float tot = sw[0] + sw[1] + sw[2] + sw[3];
    float den = fmaxf(sqrtf(tot), 1e-12f);
    float4 o4;
    o4.x = v.x / den; o4.y = v.y / den; o4.z = v.z / den; o4.w = v.w / den;
    dst[tid] = o4;
}

// ============================================================
// K4: Gram = P * P^T, 64x64 tiles, 4x4 micro-tile, k-split 16
// (disjoint partial outputs -> no atomics, no pre-zero)
// ============================================================
__global__ __launch_bounds__(256) void k4_gemm()
{
    __shared__ float As[16][68];
    __shared__ float Bs[16][68];
    int tid = threadIdx.x;
    int tx = tid & 15, ty = tid >> 4;
    int m0 = blockIdx.y * 64, n0 = blockIdx.x * 64, k0 = blockIdx.z * 32;
    int lr = tid >> 2, lq = tid & 3;

    float acc[4][4] = {};

#pragma unroll
    for (int kt = 0; kt < 32; kt += 16) {
        float4 av = *(const float4*)&g_P[(size_t)(m0 + lr) * ND + k0 + kt + lq * 4];
        float4 bv = *(const float4*)&g_P[(size_t)(n0 + lr) * ND + k0 + kt + lq * 4];
        As[lq * 4 + 0][lr] = av.x; As[lq * 4 + 1][lr] = av.y;
        As[lq * 4 + 2][lr] = av.z; As[lq * 4 + 3][lr] = av.w;
        Bs[lq * 4 + 0][lr] = bv.x; Bs[lq * 4 + 1][lr] = bv.y;
        Bs[lq * 4 + 2][lr] = bv.z; Bs[lq * 4 + 3][lr] = bv.w;
        __syncthreads();
#pragma unroll
        for (int kk = 0; kk < 16; kk++) {
            float4 a  = *(const float4*)&As[kk][ty * 4];
            float4 bb = *(const float4*)&Bs[kk][tx * 4];
            float ar[4] = {a.x, a.y, a.z, a.w};
            float br[4] = {bb.x, bb.y, bb.z, bb.w};
#pragma unroll
            for (int ia = 0; ia < 4; ia++)
#pragma unroll
                for (int ib = 0; ib < 4; ib++)
                    acc[ia][ib] += ar[ia] * br[ib];
        }
        __syncthreads();
    }

    float* S = g_S16[blockIdx.z];
#pragma unroll
    for (int ia = 0; ia < 4; ia++) {
        float4 o = make_float4(acc[ia][0], acc[ia][1], acc[ia][2], acc[ia][3]);
        *(float4*)&S[(size_t)(m0 + ty * 4 + ia) * RP + n0 + tx * 4] = o;
    }
}

// ============================================================
// K4R: reduce 16 k-split partials -> g_S (all L2-resident)
// ============================================================
__global__ __launch_bounds__(256) void k4_reduce()
{
    int idx = blockIdx.x * 256 + threadIdx.x;   // float4 index
    float4 s = make_float4(0.f, 0.f, 0.f, 0.f);
#pragma unroll
    for (int p = 0; p < KSPL; p++) {
        float4 v = ((const float4*)g_S16[p])[idx];
        s.x += v.x; s.y += v.y; s.z += v.z; s.w += v.w;
    }
    ((float4*)g_S)[idx] = s;
}

// ============================================================
// K5: per-class masked LSE + positive mean -> atomicAdd loss
// ============================================================
__global__ __launch_bounds__(256) void k5_loss(float* __restrict__ out)
{
    __shared__ unsigned char pres[NR];
    __shared__ float red0[256], red1[256], red2[256];
    int tid = threadIdx.x;
    int c = blockIdx.x;
    for (int idx = tid; idx < NR; idx += 256) {
        int t = g_cnt4[0][idx] + g_cnt4[1][idx] + g_cnt4[2][idx] + g_cnt4[3][idx];
        pres[idx] = (t > 0) ? 1 : 0;
    }
    __syncthreads();

    int i = tid >> 4, j = tid & 15;
    float s_all = 0.f, s_diag = 0.f, p_sum = 0.f;
    int r1 = i * NC + c;
    if (pres[r1]) {
        for (int e = 0; e < NC; e++) {
            int r2 = j * NC + e;
            if (pres[r2]) {
                float v = g_S[(size_t)r1 * RP + r2] / 0.1f;
                float ev = expf(v);
                s_all += ev;
                if (e == c) { s_diag += ev; p_sum += v; }
            }
        }
    }
    red0[tid] = s_all; red1[tid] = s_diag; red2[tid] = p_sum;
    __syncthreads();
    for (int st = 128; st; st >>= 1) {
        if (tid < st) {
            red0[tid] += red0[tid + st];
            red1[tid] += red1[tid + st];
            red2[tid] += red2[tid + st];
        }
        __syncthreads();
    }
    if (tid == 0) {
        int nc = 0;
        for (int ii = 0; ii < NB; ii++) nc += pres[ii * NC + c];
        if (nc > 0) {
            int cnt = nc * nc;
            float lse = logf(red1[0] + red0[0]);   // logaddexp(lse_diag, lse_all)
            float pm  = red2[0] / (float)cnt;
            atomicAdd(out, lse - pm);
        }
    }
}

// ============================================================
extern "C" void kernel_launch(void* const* d_in, const int* in_sizes, int n_in,
                              void* d_out, int out_size)
{
    const float* feat   = (const float*)d_in[0];
    const int*   labels = (const int*)d_in[1];
    float*       out    = (float*)d_out;

    k1_labels<<<dim3(NB, 4), 256>>>(labels, out);
    k2_pool<<<NB * ND, 128>>>(feat);
    k3_norm<<<RP, 128>>>();
    k4_gemm<<<dim3(6, 6, KSPL), 256>>>();
    k4_reduce<<<RP * RP / 1024, 256>>>();
    k5_loss<<<NC, 256>>>(out);
}